// round 1
// baseline (speedup 1.0000x reference)
#include <cuda_runtime.h>
#include <math.h>

#define Nn 20000
#define Ee 100000
#define Bb 128
#define FIN 14
#define DIM 64
#define EFEAT 4
#define MLPH 128
#define D2 4096   // DIM*DIM
#define G3 192    // 3*DIM

// ---------------- scratch (device globals; no allocation allowed) ----------
__device__ float g_out[Nn * DIM];
__device__ float g_h[Nn * DIM];
__device__ float g_t[Ee * MLPH];
__device__ float g_ew[409600000];          // E * DIM * DIM, 1.64 GB
__device__ float g_agg[Nn * DIM];
__device__ float g_m[Nn * DIM];
__device__ float g_gi[Nn * G3];
__device__ float g_gh[Nn * G3];
__device__ float g_cnt[Nn];
__device__ int   g_gs[Bb + 1];
__device__ float g_qstar[Bb * 2 * DIM];
__device__ float g_hl[Bb * DIM];
__device__ float g_cl[Bb * DIM];
__device__ float g_escr[Nn];

__device__ __forceinline__ float sigm(float x) { return 1.f / (1.f + expf(-x)); }

// ---------------- lin0 + relu -> out, h -----------------------------------
__global__ void k_lin0(const float* __restrict__ x, const float* __restrict__ w,
                       const float* __restrict__ b) {
    int idx = blockIdx.x * blockDim.x + threadIdx.x;
    if (idx >= Nn * DIM) return;
    int n = idx >> 6, d = idx & 63;
    float acc = b[d];
#pragma unroll
    for (int i = 0; i < FIN; i++) acc += x[n * FIN + i] * w[i * DIM + d];
    float v = fmaxf(acc, 0.f);
    g_out[idx] = v;
    g_h[idx] = v;
}

// ---------------- edge MLP hidden: t = relu(ea@W1 + b1) -------------------
__global__ void k_edge_hidden(const float* __restrict__ ea, const float* __restrict__ w1,
                              const float* __restrict__ b1) {
    int idx = blockIdx.x * blockDim.x + threadIdx.x;
    if (idx >= Ee * MLPH) return;
    int e = idx >> 7, hc = idx & 127;
    float acc = b1[hc];
#pragma unroll
    for (int f = 0; f < EFEAT; f++) acc += ea[e * EFEAT + f] * w1[f * MLPH + hc];
    g_t[idx] = fmaxf(acc, 0.f);
}

// ---------------- ew = t @ W2 + b2  (M=E, N=4096, K=128) ------------------
__global__ void __launch_bounds__(256, 2)
k_ew_gemm(const float* __restrict__ Bw, const float* __restrict__ bias) {
    const int BK = 8;
    __shared__ float As[BK][128];
    __shared__ float Bs[BK][128];
    int tid = threadIdx.x;
    int row0 = blockIdx.y * 128;
    int col0 = blockIdx.x * 128;
    int tr = (tid >> 4) << 3;   // 0..120
    int tc = (tid & 15) << 3;   // 0..120
    float acc[8][8] = {};
    int arow = tid >> 1, acol = (tid & 1) << 2;
    int brow = tid >> 5, bcol = (tid & 31) << 2;

    for (int k0 = 0; k0 < 128; k0 += BK) {
        float4 av = make_float4(0.f, 0.f, 0.f, 0.f);
        if (row0 + arow < Ee)
            av = *(const float4*)(g_t + (size_t)(row0 + arow) * 128 + k0 + acol);
        As[acol + 0][arow] = av.x;
        As[acol + 1][arow] = av.y;
        As[acol + 2][arow] = av.z;
        As[acol + 3][arow] = av.w;
        float4 bv = *(const float4*)(Bw + (size_t)(k0 + brow) * D2 + col0 + bcol);
        *(float4*)(&Bs[brow][bcol]) = bv;
        __syncthreads();
#pragma unroll
        for (int kk = 0; kk < BK; kk++) {
            float ar[8], br[8];
            float4 a0 = *(float4*)&As[kk][tr];
            float4 a1 = *(float4*)&As[kk][tr + 4];
            ar[0] = a0.x; ar[1] = a0.y; ar[2] = a0.z; ar[3] = a0.w;
            ar[4] = a1.x; ar[5] = a1.y; ar[6] = a1.z; ar[7] = a1.w;
            float4 b0 = *(float4*)&Bs[kk][tc];
            float4 b1 = *(float4*)&Bs[kk][tc + 4];
            br[0] = b0.x; br[1] = b0.y; br[2] = b0.z; br[3] = b0.w;
            br[4] = b1.x; br[5] = b1.y; br[6] = b1.z; br[7] = b1.w;
#pragma unroll
            for (int i = 0; i < 8; i++)
#pragma unroll
                for (int j = 0; j < 8; j++) acc[i][j] += ar[i] * br[j];
        }
        __syncthreads();
    }
#pragma unroll
    for (int i = 0; i < 8; i++) {
        int r = row0 + tr + i;
        if (r < Ee) {
            float4 v0, v1;
            v0.x = acc[i][0] + bias[col0 + tc + 0];
            v0.y = acc[i][1] + bias[col0 + tc + 1];
            v0.z = acc[i][2] + bias[col0 + tc + 2];
            v0.w = acc[i][3] + bias[col0 + tc + 3];
            v1.x = acc[i][4] + bias[col0 + tc + 4];
            v1.y = acc[i][5] + bias[col0 + tc + 5];
            v1.z = acc[i][6] + bias[col0 + tc + 6];
            v1.w = acc[i][7] + bias[col0 + tc + 7];
            *(float4*)(g_ew + (size_t)r * D2 + col0 + tc) = v0;
            *(float4*)(g_ew + (size_t)r * D2 + col0 + tc + 4) = v1;
        }
    }
}

// ---------------- zero helpers --------------------------------------------
__global__ void k_zero_agg() {
    int idx = blockIdx.x * blockDim.x + threadIdx.x;
    if (idx < Nn * DIM) g_agg[idx] = 0.f;
}
__global__ void k_zero_cnt() {
    int idx = blockIdx.x * blockDim.x + threadIdx.x;
    if (idx < Nn) g_cnt[idx] = 0.f;
}
__global__ void k_zero_s2s() {
    int idx = blockIdx.x * blockDim.x + threadIdx.x;
    if (idx < Bb * 2 * DIM) g_qstar[idx] = 0.f;
    if (idx < Bb * DIM) { g_hl[idx] = 0.f; g_cl[idx] = 0.f; }
}

// ---------------- in-degree counts -----------------------------------------
__global__ void k_count(const int* __restrict__ ei) {
    int e = blockIdx.x * blockDim.x + threadIdx.x;
    if (e < Ee) atomicAdd(&g_cnt[ei[Ee + e]], 1.f);
}

// ---------------- per-edge matmul + scatter-add ----------------------------
__global__ void k_msg(const int* __restrict__ ei) {
    int eg = threadIdx.x >> 6;      // 4 edges per block
    int o = threadIdx.x & 63;
    int e = blockIdx.x * 4 + eg;
    __shared__ float xs[4][64];
    int dst = 0;
    if (e < Ee) {
        int src = ei[e];
        dst = ei[Ee + e];
        xs[eg][o] = g_out[src * DIM + o];
    }
    __syncthreads();
    if (e >= Ee) return;
    const float* ew = g_ew + (size_t)e * D2 + o;
    float acc = 0.f;
#pragma unroll 8
    for (int i = 0; i < 64; i++) acc += xs[eg][i] * ew[(size_t)i * 64];
    atomicAdd(&g_agg[dst * DIM + o], acc);
}

// ---------------- m = relu(agg/cnt + out@CR + cb) --------------------------
__global__ void k_conv(const float* __restrict__ cr, const float* __restrict__ cb) {
    int d = threadIdx.x;            // 64 threads
    int n0 = blockIdx.x * 16;
    __shared__ float os[16][DIM];
#pragma unroll
    for (int r = 0; r < 16; r++) {
        int n = n0 + r;
        os[r][d] = (n < Nn) ? g_out[n * DIM + d] : 0.f;
    }
    __syncthreads();
    float acc[16];
#pragma unroll
    for (int r = 0; r < 16; r++) acc[r] = 0.f;
    for (int i = 0; i < 64; i++) {
        float w = cr[i * DIM + d];
#pragma unroll
        for (int r = 0; r < 16; r++) acc[r] += os[r][i] * w;
    }
    float bd = cb[d];
#pragma unroll
    for (int r = 0; r < 16; r++) {
        int n = n0 + r;
        if (n < Nn) {
            float c = fmaxf(g_cnt[n], 1.f);
            g_m[n * DIM + d] = fmaxf(g_agg[n * DIM + d] / c + acc[r] + bd, 0.f);
        }
    }
}

// ---------------- GRU gate GEMMs: gi = m@Wi+bi, gh = h@Wh+bh ---------------
__global__ void k_gates(const float* __restrict__ wi, const float* __restrict__ wh,
                        const float* __restrict__ bi, const float* __restrict__ bh) {
    int g = threadIdx.x;            // 192 threads
    int n0 = blockIdx.x * 16;
    __shared__ float ms[16][DIM], hs[16][DIM];
    for (int idx = g; idx < 16 * DIM; idx += 192) {
        int r = idx >> 6, d = idx & 63;
        int n = n0 + r;
        ms[r][d] = (n < Nn) ? g_m[n * DIM + d] : 0.f;
        hs[r][d] = (n < Nn) ? g_h[n * DIM + d] : 0.f;
    }
    __syncthreads();
    float ai[16], ah[16];
#pragma unroll
    for (int r = 0; r < 16; r++) { ai[r] = 0.f; ah[r] = 0.f; }
    for (int i = 0; i < 64; i++) {
        float wiv = wi[i * G3 + g], whv = wh[i * G3 + g];
#pragma unroll
        for (int r = 0; r < 16; r++) {
            ai[r] += ms[r][i] * wiv;
            ah[r] += hs[r][i] * whv;
        }
    }
    float biv = bi[g], bhv = bh[g];
#pragma unroll
    for (int r = 0; r < 16; r++) {
        int n = n0 + r;
        if (n < Nn) {
            g_gi[n * G3 + g] = ai[r] + biv;
            g_gh[n * G3 + g] = ah[r] + bhv;
        }
    }
}

// ---------------- GRU elementwise update -----------------------------------
__global__ void k_gru() {
    int idx = blockIdx.x * blockDim.x + threadIdx.x;
    if (idx >= Nn * DIM) return;
    int n = idx >> 6, d = idx & 63;
    const float* gi = g_gi + n * G3;
    const float* gh = g_gh + n * G3;
    float r = sigm(gi[d] + gh[d]);
    float z = sigm(gi[64 + d] + gh[64 + d]);
    float nn = tanhf(gi[128 + d] + r * gh[128 + d]);
    float h = g_h[idx];
    float hn = (1.f - z) * nn + z * h;
    g_h[idx] = hn;
    g_out[idx] = hn;
}

// ---------------- per-graph node ranges (batch is sorted) ------------------
__global__ void k_ranges(const int* __restrict__ batch) {
    int n = blockIdx.x * blockDim.x + threadIdx.x;
    if (n >= Nn) return;
    int bn = batch[n];
    int bp = (n == 0) ? -1 : batch[n - 1];
    for (int b = bp + 1; b <= bn; b++) g_gs[b] = n;
    if (n == Nn - 1)
        for (int b = bn + 1; b <= Bb; b++) g_gs[b] = Nn;
}

// ---------------- Set2Set LSTM cell ----------------------------------------
__global__ void k_lstm(const float* __restrict__ wi, const float* __restrict__ wh,
                       const float* __restrict__ bi, const float* __restrict__ bh) {
    int b = blockIdx.x;
    int g = threadIdx.x;            // 256 threads
    __shared__ float qs[128], hls[64], gate[256];
    if (g < 128) qs[g] = g_qstar[b * 128 + g];
    if (g < 64) hls[g] = g_hl[b * 64 + g];
    __syncthreads();
    float acc = bi[g] + bh[g];
    for (int i = 0; i < 128; i++) acc += qs[i] * wi[i * 256 + g];
    for (int i = 0; i < 64; i++) acc += hls[i] * wh[i * 256 + g];
    gate[g] = acc;
    __syncthreads();
    if (g < 64) {
        float iv = sigm(gate[g]);
        float fv = sigm(gate[64 + g]);
        float gv = tanhf(gate[128 + g]);
        float ov = sigm(gate[192 + g]);
        float c = fv * g_cl[b * 64 + g] + iv * gv;
        g_cl[b * 64 + g] = c;
        g_hl[b * 64 + g] = ov * tanhf(c);
    }
}

// ---------------- Set2Set attention + readout ------------------------------
__global__ void k_attend() {
    int b = blockIdx.x;
    int t = threadIdx.x;            // 256 threads
    __shared__ float q[64];
    __shared__ float red[256];
    __shared__ float rs[4][64];
    if (t < 64) q[t] = g_hl[b * 64 + t];
    int s = g_gs[b], epos = g_gs[b + 1];
    __syncthreads();

    // pass 1: e[n] = out[n] . q ; block max
    float lmax = -INFINITY;
    for (int n = s + t; n < epos; n += 256) {
        const float* orow = g_out + (size_t)n * 64;
        float acc = 0.f;
#pragma unroll
        for (int d = 0; d < 64; d++) acc += orow[d] * q[d];
        g_escr[n] = acc;
        lmax = fmaxf(lmax, acc);
    }
    red[t] = lmax;
    __syncthreads();
    for (int st = 128; st > 0; st >>= 1) {
        if (t < st) red[t] = fmaxf(red[t], red[t + st]);
        __syncthreads();
    }
    float emax = red[0];
    __syncthreads();

    // pass 2: a[n] = exp(e - emax); block sum
    float lsum = 0.f;
    for (int n = s + t; n < epos; n += 256) {
        float a = expf(g_escr[n] - emax);
        g_escr[n] = a;
        lsum += a;
    }
    red[t] = lsum;
    __syncthreads();
    for (int st = 128; st > 0; st >>= 1) {
        if (t < st) red[t] += red[t + st];
        __syncthreads();
    }
    float inv = 1.f / fmaxf(red[0], 1e-16f);
    __syncthreads();

    // pass 3: r_vec = sum a[n]*out[n]
    int d = t & 63, slot = t >> 6;
    float acc = 0.f;
    for (int n = s + slot; n < epos; n += 4) acc += g_escr[n] * g_out[(size_t)n * 64 + d];
    rs[slot][d] = acc;
    __syncthreads();
    if (t < 64) {
        float r = (rs[0][t] + rs[1][t] + rs[2][t] + rs[3][t]) * inv;
        g_qstar[b * 128 + t] = q[t];
        g_qstar[b * 128 + 64 + t] = r;
    }
}

// ---------------- output head ----------------------------------------------
__global__ void k_head(const float* __restrict__ w1, const float* __restrict__ b1,
                       const float* __restrict__ w2, const float* __restrict__ b2,
                       float* __restrict__ out) {
    int b = blockIdx.x;
    int d = threadIdx.x;            // 64 threads
    __shared__ float qs[128];
    __shared__ float red[64];
    qs[d] = g_qstar[b * 128 + d];
    qs[64 + d] = g_qstar[b * 128 + 64 + d];
    __syncthreads();
    float acc = b1[d];
    for (int i = 0; i < 128; i++) acc += qs[i] * w1[i * 64 + d];
    float h1 = fmaxf(acc, 0.f);
    red[d] = h1 * w2[d];
    __syncthreads();
    for (int st = 32; st > 0; st >>= 1) {
        if (d < st) red[d] += red[d + st];
        __syncthreads();
    }
    if (d == 0) out[b] = red[0] + b2[0];
}

// ---------------- launch ----------------------------------------------------
extern "C" void kernel_launch(void* const* d_in, const int* in_sizes, int n_in,
                              void* d_out, int out_size) {
    const float* x        = (const float*)d_in[0];
    const float* ea       = (const float*)d_in[1];
    const int*   ei       = (const int*)d_in[2];
    const int*   batch    = (const int*)d_in[3];
    const float* lin0_w   = (const float*)d_in[4];
    const float* lin0_b   = (const float*)d_in[5];
    const float* mlp_w1   = (const float*)d_in[6];
    const float* mlp_b1   = (const float*)d_in[7];
    const float* mlp_w2   = (const float*)d_in[8];
    const float* mlp_b2   = (const float*)d_in[9];
    const float* conv_root= (const float*)d_in[10];
    const float* conv_bias= (const float*)d_in[11];
    const float* gru_wi   = (const float*)d_in[12];
    const float* gru_wh   = (const float*)d_in[13];
    const float* gru_bi   = (const float*)d_in[14];
    const float* gru_bh   = (const float*)d_in[15];
    const float* lstm_wi  = (const float*)d_in[16];
    const float* lstm_wh  = (const float*)d_in[17];
    const float* lstm_bi  = (const float*)d_in[18];
    const float* lstm_bh  = (const float*)d_in[19];
    const float* lin1_w   = (const float*)d_in[20];
    const float* lin1_b   = (const float*)d_in[21];
    const float* lin2_w   = (const float*)d_in[22];
    const float* lin2_b   = (const float*)d_in[23];
    float* out = (float*)d_out;

    k_lin0<<<(Nn * DIM + 255) / 256, 256>>>(x, lin0_w, lin0_b);
    k_edge_hidden<<<(Ee * MLPH + 255) / 256, 256>>>(ea, mlp_w1, mlp_b1);
    {
        dim3 grid(D2 / 128, (Ee + 127) / 128);
        k_ew_gemm<<<grid, 256>>>(mlp_w2, mlp_b2);
    }
    k_zero_cnt<<<(Nn + 255) / 256, 256>>>();
    k_count<<<(Ee + 255) / 256, 256>>>(ei);

    for (int s = 0; s < 3; s++) {
        k_zero_agg<<<(Nn * DIM + 255) / 256, 256>>>();
        k_msg<<<(Ee + 3) / 4, 256>>>(ei);
        k_conv<<<(Nn + 15) / 16, 64>>>(conv_root, conv_bias);
        k_gates<<<(Nn + 15) / 16, 192>>>(gru_wi, gru_wh, gru_bi, gru_bh);
        k_gru<<<(Nn * DIM + 255) / 256, 256>>>();
    }

    k_ranges<<<(Nn + 255) / 256, 256>>>(batch);
    k_zero_s2s<<<(Bb * 2 * DIM + 255) / 256, 256>>>();
    for (int it = 0; it < 3; it++) {
        k_lstm<<<Bb, 256>>>(lstm_wi, lstm_wh, lstm_bi, lstm_bh);
        k_attend<<<Bb, 256>>>();
    }
    k_head<<<Bb, 64>>>(lin1_w, lin1_b, lin2_w, lin2_b, out);
}